// round 3
// baseline (speedup 1.0000x reference)
#include <cuda_runtime.h>
#include <cstdint>

// GriddingDistance: trilinear scatter of two point clouds into voxel grids.
// SCALE=128, L=131, V=L^3=2248091, B=16, N=32768.
// Output: [pred_grid (16*V floats) | gt_grid (16*V floats)].
//
// Strategy: bin points by x-slab (key independent of the data-dependent min),
// then one CTA per (cloud,batch,x-plane) accumulates a 131x131 plane in smem
// and writes it with pure coalesced stores — no global atomics, no memset.

#define SCALE_F   64.0f
#define GRID_L    131
#define GRID_P    (GRID_L * GRID_L)            // 17161 floats per plane
#define GRID_V    (GRID_L * GRID_L * GRID_L)   // 2248091
#define BATCH     16
#define NPTS      32768
#define NCB       32                            // 2 clouds * 16 batches
#define NKEY      128                           // floor(64x) in [-64,63] -> key in [0,128)
#define CAP       512                           // bin capacity (mean 256, P(overflow)~e^-99)

__device__ int            g_min[3] = {0x7fffffff, 0x7fffffff, 0x7fffffff};
__device__ int            g_hist[NCB * NKEY];           // zero-init at load; reset kernel re-zeros
__device__ unsigned short g_idx[NCB * NKEY * CAP];      // point index within batch

// ---- launch 0: reset state for this (replayed) call ------------------------
__global__ void reset_kernel() {
    int t = threadIdx.x + blockIdx.x * blockDim.x;
    if (t < 3) g_min[t] = 0x7fffffff;
    for (int i = t; i < NCB * NKEY; i += blockDim.x * gridDim.x) g_hist[i] = 0;
}

// ---- launch 1: per-axis integer min over both clouds -----------------------
// floor(min) == min(floor) -> integer reduction. Padding points included
// (reference computes mins before masking).
__global__ void min_kernel(const float* __restrict__ pred,
                           const float* __restrict__ gt) {
    const int total = BATCH * NPTS;
    int tid = blockIdx.x * blockDim.x + threadIdx.x;
    int stride = gridDim.x * blockDim.x;

    int mn0 = 0x7fffffff, mn1 = 0x7fffffff, mn2 = 0x7fffffff;
    for (int i = tid; i < total; i += stride) {
        const float* p = pred + 3 * i;
        const float* g = gt   + 3 * i;
        mn0 = min(mn0, min((int)floorf(p[0] * SCALE_F), (int)floorf(g[0] * SCALE_F)));
        mn1 = min(mn1, min((int)floorf(p[1] * SCALE_F), (int)floorf(g[1] * SCALE_F)));
        mn2 = min(mn2, min((int)floorf(p[2] * SCALE_F), (int)floorf(g[2] * SCALE_F)));
    }
    #pragma unroll
    for (int off = 16; off > 0; off >>= 1) {
        mn0 = min(mn0, __shfl_xor_sync(0xffffffffu, mn0, off));
        mn1 = min(mn1, __shfl_xor_sync(0xffffffffu, mn1, off));
        mn2 = min(mn2, __shfl_xor_sync(0xffffffffu, mn2, off));
    }
    if ((threadIdx.x & 31) == 0) {
        atomicMin(&g_min[0], mn0);
        atomicMin(&g_min[1], mn1);
        atomicMin(&g_min[2], mn2);
    }
}

// ---- launch 2: bin every (non-padding) point by its x-slab -----------------
// 8 CTAs per (cloud,batch); key = floor(64x)+64, no dependency on g_min.
__global__ void bin_kernel(const float* __restrict__ pred,
                           const float* __restrict__ gt) {
    int cb = blockIdx.x >> 3;            // 0..31
    int c  = cb >> 4;
    int b  = cb & 15;
    const float* cloud = (c ? gt : pred) + 3 * (size_t)b * NPTS;
    int base_pt = (blockIdx.x & 7) * (NPTS / 8);

    for (int i = threadIdx.x; i < NPTS / 8; i += blockDim.x) {
        int pi = base_pt + i;
        float x = cloud[3 * pi + 0] * SCALE_F;
        float y = cloud[3 * pi + 1] * SCALE_F;
        float z = cloud[3 * pi + 2] * SCALE_F;
        if (x + y + z == 0.0f) continue;            // padding point
        int key = (int)floorf(x) + 64;              // 0..127
        int bin = cb * NKEY + key;
        int pos = atomicAdd(&g_hist[bin], 1);
        if (pos < CAP) g_idx[bin * CAP + pos] = (unsigned short)pi;
    }
}

// ---- launch 3: accumulate one x-plane in smem, write it out ----------------
// CTA id -> (cb, ixg). Plane ixg receives: points with lower-corner grid-x
// == ixg (weight 1-ax) and == ixg-1 (weight ax).
__global__ void slab_kernel(const float* __restrict__ pred,
                            const float* __restrict__ gt,
                            float* __restrict__ out) {
    extern __shared__ float plane[];     // GRID_P floats = 68644 B

    int ixg = blockIdx.x % GRID_L;
    int cb  = blockIdx.x / GRID_L;
    int c   = cb >> 4;
    int b   = cb & 15;
    const float* cloud = (c ? gt : pred) + 3 * (size_t)b * NPTS;

    for (int i = threadIdx.x; i < GRID_P; i += blockDim.x) plane[i] = 0.0f;
    __syncthreads();

    int m0 = g_min[0], m1 = g_min[1], m2 = g_min[2];

    #pragma unroll
    for (int s = 0; s < 2; s++) {
        // lower-corner grid-x = ixg - s  ->  key = (ixg - s) + (m0 - 1) + 64
        int key = ixg - s + m0 + 63;
        if (key < 0 || key >= NKEY) continue;
        int bin = cb * NKEY + key;
        int cnt = min(g_hist[bin], CAP);
        for (int j = threadIdx.x; j < cnt; j += blockDim.x) {
            int pi = g_idx[bin * CAP + j];
            float x = cloud[3 * pi + 0] * SCALE_F;
            float y = cloud[3 * pi + 1] * SCALE_F;
            float z = cloud[3 * pi + 2] * SCALE_F;
            float ax = x - floorf(x);
            float wx = s ? ax : 1.0f - ax;
            float fy = floorf(y), fz = floorf(z);
            float ay = y - fy, az = z - fz;
            int iy = (int)fy - (m1 - 1);
            int iz = (int)fz - (m2 - 1);
            float* q = plane + iy * GRID_L + iz;
            atomicAdd(q,              wx * (1.0f - ay) * (1.0f - az));
            atomicAdd(q + 1,          wx * (1.0f - ay) * az);
            atomicAdd(q + GRID_L,     wx * ay * (1.0f - az));
            atomicAdd(q + GRID_L + 1, wx * ay * az);
        }
    }
    __syncthreads();

    // Write the plane: zeros included -> no separate memset, no global RMW.
    size_t base = (size_t)cb * GRID_V + (size_t)ixg * GRID_P;
    float* dst = out + base;
    int peel = (4 - ((int)(base & 3))) & 3;          // to 16B-align dst
    for (int i = threadIdx.x; i < peel; i += blockDim.x) dst[i] = plane[i];
    int n4 = (GRID_P - peel) >> 2;
    float4* d4 = (float4*)(dst + peel);
    for (int i = threadIdx.x; i < n4; i += blockDim.x) {
        int k = peel + 4 * i;
        d4[i] = make_float4(plane[k], plane[k + 1], plane[k + 2], plane[k + 3]);
    }
    for (int i = peel + 4 * n4 + threadIdx.x; i < GRID_P; i += blockDim.x)
        dst[i] = plane[i];
}

extern "C" void kernel_launch(void* const* d_in, const int* in_sizes, int n_in,
                              void* d_out, int out_size) {
    const float* pred = (const float*)d_in[0];
    const float* gt   = (const float*)d_in[1];
    float* out        = (float*)d_out;

    static const size_t kSmem = GRID_P * sizeof(float);   // 68644 B
    cudaFuncSetAttribute(slab_kernel,
                         cudaFuncAttributeMaxDynamicSharedMemorySize,
                         (int)kSmem);

    reset_kernel<<<8, 512>>>();                           // launch 0
    min_kernel<<<512, 256>>>(pred, gt);                   // launch 1
    bin_kernel<<<NCB * 8, 256>>>(pred, gt);               // launch 2
    slab_kernel<<<NCB * GRID_L, 256, kSmem>>>(pred, gt, out);  // launch 3 (profiled)
}

// round 4
// speedup vs baseline: 1.6860x; 1.6860x over previous
#include <cuda_runtime.h>
#include <cstdint>

// GriddingDistance: trilinear scatter of two point clouds into voxel grids.
// SCALE=128, L=131, V=L^3, B=16, N=32768.
// Output: [pred_grid (16*V) | gt_grid (16*V)] floats.
//
// 3 launches:
//  1) min_kernel : per-block partial mins (plain stores) + zero g_hist
//  2) bin_kernel : finalize g_min (block 0) + bin payloads by x-slab
//  3) slab_kernel: one CTA per (cloud,batch,x-plane,y-half); accumulate
//     66x131 half-plane in smem (atomics), write coalesced. No global
//     atomics, no memset, zeros written as part of the plane store.

#define SCALE_F   64.0f
#define GRID_L    131
#define GRID_P    (GRID_L * GRID_L)
#define GRID_V    (GRID_L * GRID_L * GRID_L)
#define BATCH     16
#define NPTS      32768
#define NCB       32
#define NKEY      128
#define CAP       512
#define MINBLK    128
#define ROWS0     66                 // half 0 owns rows 0..65
#define ROWS1     65                 // half 1 owns rows 66..130

__device__ int    g_part[MINBLK * 3];        // per-block partial mins
__device__ int    g_min[3];                  // finalized in bin_kernel blk 0
__device__ int    g_hist[NCB * NKEY];        // zeroed in min_kernel
__device__ float4 g_pay[NCB * NKEY * CAP];   // {ax, ay, az, pack(fy,fz)}

// ---- launch 1: block-partial per-axis integer min + zero hist --------------
__global__ void min_kernel(const float* __restrict__ pred,
                           const float* __restrict__ gt) {
    const int total = BATCH * NPTS;
    int gtid = blockIdx.x * blockDim.x + threadIdx.x;
    int gsz  = gridDim.x * blockDim.x;

    // zero the histogram for this call (consumed next launch)
    for (int i = gtid; i < NCB * NKEY; i += gsz) g_hist[i] = 0;

    int mn0 = 0x7fffffff, mn1 = 0x7fffffff, mn2 = 0x7fffffff;
    for (int i = gtid; i < total; i += gsz) {
        const float* p = pred + 3 * i;
        const float* g = gt   + 3 * i;
        mn0 = min(mn0, min((int)floorf(p[0] * SCALE_F), (int)floorf(g[0] * SCALE_F)));
        mn1 = min(mn1, min((int)floorf(p[1] * SCALE_F), (int)floorf(g[1] * SCALE_F)));
        mn2 = min(mn2, min((int)floorf(p[2] * SCALE_F), (int)floorf(g[2] * SCALE_F)));
    }
    #pragma unroll
    for (int off = 16; off > 0; off >>= 1) {
        mn0 = min(mn0, __shfl_xor_sync(0xffffffffu, mn0, off));
        mn1 = min(mn1, __shfl_xor_sync(0xffffffffu, mn1, off));
        mn2 = min(mn2, __shfl_xor_sync(0xffffffffu, mn2, off));
    }
    __shared__ int s0[8], s1[8], s2[8];
    int w = threadIdx.x >> 5, l = threadIdx.x & 31;
    if (l == 0) { s0[w] = mn0; s1[w] = mn1; s2[w] = mn2; }
    __syncthreads();
    if (w == 0) {
        int a = (l < 8) ? s0[l] : 0x7fffffff;
        int b = (l < 8) ? s1[l] : 0x7fffffff;
        int c = (l < 8) ? s2[l] : 0x7fffffff;
        #pragma unroll
        for (int off = 4; off > 0; off >>= 1) {
            a = min(a, __shfl_xor_sync(0xffffffffu, a, off));
            b = min(b, __shfl_xor_sync(0xffffffffu, b, off));
            c = min(c, __shfl_xor_sync(0xffffffffu, c, off));
        }
        if (l == 0) {
            g_part[blockIdx.x * 3 + 0] = a;
            g_part[blockIdx.x * 3 + 1] = b;
            g_part[blockIdx.x * 3 + 2] = c;
        }
    }
}

// ---- launch 2: finalize min (blk 0) + bin payloads by x-slab ---------------
__global__ void bin_kernel(const float* __restrict__ pred,
                           const float* __restrict__ gt) {
    // block 0, warp 0: reduce the 128 partials into g_min (plain stores)
    if (blockIdx.x == 0 && threadIdx.x < 32) {
        int l = threadIdx.x;
        int a = 0x7fffffff, b = 0x7fffffff, c = 0x7fffffff;
        for (int i = l; i < MINBLK; i += 32) {
            a = min(a, g_part[i * 3 + 0]);
            b = min(b, g_part[i * 3 + 1]);
            c = min(c, g_part[i * 3 + 2]);
        }
        #pragma unroll
        for (int off = 16; off > 0; off >>= 1) {
            a = min(a, __shfl_xor_sync(0xffffffffu, a, off));
            b = min(b, __shfl_xor_sync(0xffffffffu, b, off));
            c = min(c, __shfl_xor_sync(0xffffffffu, c, off));
        }
        if (l == 0) { g_min[0] = a; g_min[1] = b; g_min[2] = c; }
    }

    int cb = blockIdx.x >> 3;
    int c  = cb >> 4;
    int b  = cb & 15;
    const float* cloud = (c ? gt : pred) + 3 * (size_t)b * NPTS;
    int base_pt = (blockIdx.x & 7) * (NPTS / 8);

    for (int i = threadIdx.x; i < NPTS / 8; i += blockDim.x) {
        int pi = base_pt + i;
        float x = cloud[3 * pi + 0] * SCALE_F;
        float y = cloud[3 * pi + 1] * SCALE_F;
        float z = cloud[3 * pi + 2] * SCALE_F;
        if (x + y + z == 0.0f) continue;            // padding point
        float fx = floorf(x), fy = floorf(y), fz = floorf(z);
        int key = (int)fx + 64;                     // 0..127
        if (key < 0 || key >= NKEY) continue;       // cannot happen; safety
        int bin = cb * NKEY + key;
        int pos = atomicAdd(&g_hist[bin], 1);
        if (pos < CAP) {
            unsigned pk = (unsigned)((int)fy + 64) | ((unsigned)((int)fz + 64) << 8);
            g_pay[bin * CAP + pos] =
                make_float4(x - fx, y - fy, z - fz, __uint_as_float(pk));
        }
    }
}

// ---- launch 3: accumulate one (x-plane, y-half) in smem, write it ----------
__global__ void __launch_bounds__(256) slab_kernel(float* __restrict__ out) {
    __shared__ float plane[ROWS0 * GRID_L];   // 34584 B -> 4 CTAs/SM

    int bid = blockIdx.x;
    int cb  = bid / (GRID_L * 2);
    int rem = bid - cb * (GRID_L * 2);
    int ixg = rem >> 1;
    int h   = rem & 1;
    int row_lo = h ? ROWS0 : 0;
    int nrows  = h ? ROWS1 : ROWS0;

    for (int i = threadIdx.x; i < nrows * GRID_L; i += blockDim.x)
        plane[i] = 0.0f;
    __syncthreads();

    int m0 = g_min[0], m1 = g_min[1], m2 = g_min[2];

    #pragma unroll
    for (int s = 0; s < 2; s++) {
        // points whose lower-corner grid-x == ixg - s contribute with wx
        int key = ixg - s + m0 + 63;
        if (key < 0 || key >= NKEY) continue;
        int bin = cb * NKEY + key;
        int cnt = min(g_hist[bin], CAP);
        const float4* pay = g_pay + (size_t)bin * CAP;
        for (int j = threadIdx.x; j < cnt; j += blockDim.x) {
            float4 p = pay[j];
            unsigned pk = __float_as_uint(p.w);
            int iy = (int)(pk & 0xffu)        - 63 - m1;  // lower-corner row
            int iz = (int)((pk >> 8) & 0xffu) - 63 - m2;
            float ax = p.x, ay = p.y, az = p.z;
            float wx  = s ? ax : 1.0f - ax;
            float wy0 = wx * (1.0f - ay);
            float wy1 = wx * ay;
            int r0 = iy - row_lo;
            if ((unsigned)r0 < (unsigned)nrows) {
                float* q = plane + r0 * GRID_L + iz;
                atomicAdd(q,     wy0 * (1.0f - az));
                atomicAdd(q + 1, wy0 * az);
            }
            int r1 = r0 + 1;
            if ((unsigned)r1 < (unsigned)nrows) {
                float* q = plane + r1 * GRID_L + iz;
                atomicAdd(q,     wy1 * (1.0f - az));
                atomicAdd(q + 1, wy1 * az);
            }
        }
    }
    __syncthreads();

    // coalesced store (zeros included -> no memset pass, no global RMW)
    size_t base = (size_t)cb * GRID_V + (size_t)ixg * GRID_P
                + (size_t)row_lo * GRID_L;
    int n = nrows * GRID_L;
    float* dst = out + base;
    int peel = (4 - ((int)(base & 3))) & 3;
    for (int i = threadIdx.x; i < peel; i += blockDim.x) dst[i] = plane[i];
    int n4 = (n - peel) >> 2;
    float4* d4 = (float4*)(dst + peel);
    for (int i = threadIdx.x; i < n4; i += blockDim.x) {
        int k = peel + 4 * i;
        d4[i] = make_float4(plane[k], plane[k + 1], plane[k + 2], plane[k + 3]);
    }
    for (int i = peel + 4 * n4 + threadIdx.x; i < n; i += blockDim.x)
        dst[i] = plane[i];
}

extern "C" void kernel_launch(void* const* d_in, const int* in_sizes, int n_in,
                              void* d_out, int out_size) {
    const float* pred = (const float*)d_in[0];
    const float* gt   = (const float*)d_in[1];
    float* out        = (float*)d_out;

    min_kernel<<<MINBLK, 256>>>(pred, gt);
    bin_kernel<<<NCB * 8, 256>>>(pred, gt);
    slab_kernel<<<NCB * GRID_L * 2, 256>>>(out);
}

// round 5
// speedup vs baseline: 1.8562x; 1.1010x over previous
#include <cuda_runtime.h>
#include <cstdint>

// GriddingDistance: trilinear scatter of two point clouds into voxel grids.
// SCALE=128, L=131, V=L^3, B=16, N=32768.
// Output: [pred_grid (16*V) | gt_grid (16*V)] floats.
//
// 2 launches:
//  1) bin_kernel : one pass over all points. Per-CTA partial per-axis mins
//     (plain stores) + binning into per-CTA private segments keyed by x-slab
//     (smem counters only -> no global atomics, no reset kernel needed).
//  2) slab_kernel: one CTA per (cloud,batch,x-plane,y-half). Redundantly
//     finalizes the min from the 256 partials, accumulates its half-plane in
//     smem, writes it out coalesced (zeros included -> no memset).

#define SCALE_F   64.0f
#define GRID_L    131
#define GRID_P    (GRID_L * GRID_L)
#define GRID_V    (GRID_L * GRID_L * GRID_L)
#define BATCH     16
#define NPTS      32768
#define NCB       32                  // 2 clouds * 16 batches
#define NSUB      8                   // bin CTAs per (cloud,batch)
#define NBINBLK   (NCB * NSUB)        // 256
#define PTS_BLK   (NPTS / NSUB)       // 4096
#define NKEY      128
#define SCAP      96                  // slots per (CTA,key); mean 32, P(ovf)~0
#define ROWS0     66                  // half 0: rows 0..65
#define ROWS1     65                  // half 1: rows 66..130

__device__ int    g_part[NBINBLK * 3];                 // per-CTA partial mins
__device__ int    g_cnt[NBINBLK * NKEY];               // per-CTA per-key counts
__device__ float4 g_pay[(size_t)NBINBLK * NKEY * SCAP];// {ax,ay,az,pack(fy,fz)}

// ---- launch 1: partial mins + private binning ------------------------------
__global__ void __launch_bounds__(256) bin_kernel(const float* __restrict__ pred,
                                                  const float* __restrict__ gt) {
    __shared__ int scnt[NKEY];
    __shared__ int r0s[8], r1s[8], r2s[8];

    int tid = threadIdx.x;
    int blk = blockIdx.x;
    int cb  = blk >> 3;
    int sub = blk & 7;
    int c   = cb >> 4;
    int b   = cb & 15;
    const float* cloud = (c ? gt : pred) + 3 * ((size_t)b * NPTS + sub * PTS_BLK);

    for (int i = tid; i < NKEY; i += blockDim.x) scnt[i] = 0;
    __syncthreads();

    float4* seg = g_pay + (size_t)blk * NKEY * SCAP;

    int mn0 = 0x7fffffff, mn1 = 0x7fffffff, mn2 = 0x7fffffff;
    for (int i = tid; i < PTS_BLK; i += blockDim.x) {
        float x = cloud[3 * i + 0] * SCALE_F;
        float y = cloud[3 * i + 1] * SCALE_F;
        float z = cloud[3 * i + 2] * SCALE_F;
        float fx = floorf(x), fy = floorf(y), fz = floorf(z);
        // mins include padding points (reference computes mins before masking)
        mn0 = min(mn0, (int)fx);
        mn1 = min(mn1, (int)fy);
        mn2 = min(mn2, (int)fz);
        if (x + y + z == 0.0f) continue;          // padding point: not binned
        int key = (int)fx + 64;                   // 0..127
        if ((unsigned)key >= NKEY) continue;      // safety (cannot happen)
        int pos = atomicAdd(&scnt[key], 1);
        if (pos < SCAP) {
            unsigned pk = (unsigned)((int)fy + 64) | ((unsigned)((int)fz + 64) << 8);
            seg[key * SCAP + pos] =
                make_float4(x - fx, y - fy, z - fz, __uint_as_float(pk));
        }
    }

    // reduce partial mins
    #pragma unroll
    for (int off = 16; off > 0; off >>= 1) {
        mn0 = min(mn0, __shfl_xor_sync(0xffffffffu, mn0, off));
        mn1 = min(mn1, __shfl_xor_sync(0xffffffffu, mn1, off));
        mn2 = min(mn2, __shfl_xor_sync(0xffffffffu, mn2, off));
    }
    int w = tid >> 5, l = tid & 31;
    if (l == 0) { r0s[w] = mn0; r1s[w] = mn1; r2s[w] = mn2; }
    __syncthreads();
    if (tid == 0) {
        int a = r0s[0], bb = r1s[0], cc = r2s[0];
        #pragma unroll
        for (int i = 1; i < 8; i++) {
            a = min(a, r0s[i]); bb = min(bb, r1s[i]); cc = min(cc, r2s[i]);
        }
        g_part[blk * 3 + 0] = a;
        g_part[blk * 3 + 1] = bb;
        g_part[blk * 3 + 2] = cc;
    }

    // publish clamped counts (plain stores; fully rewritten every call)
    for (int i = tid; i < NKEY; i += blockDim.x)
        g_cnt[blk * NKEY + i] = min(scnt[i], SCAP);
}

// ---- launch 2: accumulate one (x-plane, y-half) in smem, write it ----------
__global__ void __launch_bounds__(256) slab_kernel(float* __restrict__ out) {
    __shared__ float plane[ROWS0 * GRID_L];       // 34584 B
    __shared__ int   soff[NSUB + 1];
    __shared__ int   smin[3];
    __shared__ int   rs[8 * 3];

    int tid = threadIdx.x;

    // -- redundant min finalize: reduce the 256 partials ----------------------
    {
        int a = 0x7fffffff, b = 0x7fffffff, c = 0x7fffffff;
        for (int i = tid; i < NBINBLK; i += blockDim.x) {
            a = min(a, g_part[3 * i + 0]);
            b = min(b, g_part[3 * i + 1]);
            c = min(c, g_part[3 * i + 2]);
        }
        #pragma unroll
        for (int off = 16; off > 0; off >>= 1) {
            a = min(a, __shfl_xor_sync(0xffffffffu, a, off));
            b = min(b, __shfl_xor_sync(0xffffffffu, b, off));
            c = min(c, __shfl_xor_sync(0xffffffffu, c, off));
        }
        int w = tid >> 5, l = tid & 31;
        if (l == 0) { rs[w] = a; rs[8 + w] = b; rs[16 + w] = c; }
    }

    int bid = blockIdx.x;
    int cb  = bid / (GRID_L * 2);
    int rem = bid - cb * (GRID_L * 2);
    int ixg = rem >> 1;
    int h   = rem & 1;
    int row_lo = h ? ROWS0 : 0;
    int nrows  = h ? ROWS1 : ROWS0;

    for (int i = tid; i < nrows * GRID_L; i += blockDim.x) plane[i] = 0.0f;
    __syncthreads();

    if (tid == 0) {
        int a = rs[0], b = rs[8], c = rs[16];
        #pragma unroll
        for (int i = 1; i < 8; i++) {
            a = min(a, rs[i]); b = min(b, rs[8 + i]); c = min(c, rs[16 + i]);
        }
        smin[0] = a; smin[1] = b; smin[2] = c;
    }
    __syncthreads();
    int m0 = smin[0], m1 = smin[1], m2 = smin[2];

    #pragma unroll
    for (int s = 0; s < 2; s++) {
        // points with lower-corner grid-x == ixg - s contribute with weight wx
        int key = ixg - s + m0 + 63;
        if (key < 0 || key >= NKEY) continue;

        // prefix over the 8 sub-segments of this (cloud,batch)
        if (tid == 0) {
            int acc = 0;
            soff[0] = 0;
            #pragma unroll
            for (int u = 0; u < NSUB; u++) {
                acc += g_cnt[(cb * NSUB + u) * NKEY + key];
                soff[u + 1] = acc;
            }
        }
        __syncthreads();
        int total = soff[NSUB];

        for (int j = tid; j < total; j += blockDim.x) {
            int sub = 0;
            #pragma unroll
            for (int u = 1; u < NSUB; u++) sub += (j >= soff[u]);
            int local = j - soff[sub];
            float4 p = g_pay[((size_t)(cb * NSUB + sub) * NKEY + key) * SCAP + local];

            unsigned pk = __float_as_uint(p.w);
            int iy = (int)(pk & 0xffu)        - 63 - m1;   // lower-corner row
            int iz = (int)((pk >> 8) & 0xffu) - 63 - m2;
            float ax = p.x, ay = p.y, az = p.z;
            float wx  = s ? ax : 1.0f - ax;
            float wy0 = wx * (1.0f - ay);
            float wy1 = wx * ay;

            int r0 = iy - row_lo;
            if ((unsigned)r0 < (unsigned)nrows) {
                float* q = plane + r0 * GRID_L + iz;
                atomicAdd(q,     wy0 * (1.0f - az));
                atomicAdd(q + 1, wy0 * az);
            }
            int r1 = r0 + 1;
            if ((unsigned)r1 < (unsigned)nrows) {
                float* q = plane + r1 * GRID_L + iz;
                atomicAdd(q,     wy1 * (1.0f - az));
                atomicAdd(q + 1, wy1 * az);
            }
        }
        __syncthreads();
    }

    // -- coalesced store: zeros included -> no memset, no global RMW ---------
    size_t base = (size_t)cb * GRID_V + (size_t)ixg * GRID_P
                + (size_t)row_lo * GRID_L;
    int n = nrows * GRID_L;
    float* dst = out + base;
    int peel = (4 - ((int)(base & 3))) & 3;
    for (int i = tid; i < peel; i += blockDim.x) dst[i] = plane[i];
    int n4 = (n - peel) >> 2;
    float4* d4 = (float4*)(dst + peel);
    for (int i = tid; i < n4; i += blockDim.x) {
        int k = peel + 4 * i;
        d4[i] = make_float4(plane[k], plane[k + 1], plane[k + 2], plane[k + 3]);
    }
    for (int i = peel + 4 * n4 + tid; i < n; i += blockDim.x)
        dst[i] = plane[i];
}

extern "C" void kernel_launch(void* const* d_in, const int* in_sizes, int n_in,
                              void* d_out, int out_size) {
    const float* pred = (const float*)d_in[0];
    const float* gt   = (const float*)d_in[1];
    float* out        = (float*)d_out;

    bin_kernel<<<NBINBLK, 256>>>(pred, gt);
    slab_kernel<<<NCB * GRID_L * 2, 256>>>(out);
}